// round 13
// baseline (speedup 1.0000x reference)
#include <cuda_runtime.h>
#include <cuda_fp16.h>
#include <cstdint>

// DynamicPooling R13: R12 structure with sm_103-legal reduction.
// Row dot reduced via fixed-point redux.sync.add.s32 (integer redux IS
// supported on sm_103; f32 redux is not). B=64, N=4096, D=256.
// x f32 [B,N,D], m f32 [B,N,1]. Out: w [B,N], s [B,D].
//
// Pipeline per group of 16 batches:
//   fill(g):  x f32 -> y=m*x fp16 cache + sigma1 partials   (DRAM-bound)
//   reuse x3: head-combine -> s; b += dot(s,y); next sigma   (issue-bound)
// Fill on side stream (fork-join events). Reuse kernel: launch_bounds(256,5),
// PF=2, s in registers, one-redux row dots.

namespace {
constexpr int Bb = 64;
constexpr int Nn = 4096;
constexpr int Dd = 256;
constexpr int NCHUNK = 32;            // N-chunks per batch
constexpr int ROWS = Nn / NCHUNK;     // 128 rows per block
constexpr int WARPS = 8;
constexpr int RPW = ROWS / WARPS;     // 16 rows per warp
constexpr int GRP = 16;               // batches per group
constexpr int NGRP = Bb / GRP;        // 4 groups
constexpr int PFF = 3;                // prefetch depth, fill (DRAM)
constexpr int PFR = 2;                // prefetch depth, reuse (L2)
constexpr float FXS = 4194304.0f;     // 2^22 fixed-point scale
constexpr float FXI = 1.0f / 4194304.0f;
}

__device__ __half g_y[(size_t)Bb * Nn * Dd];  // fp16 cache of m*x (128MB)
__device__ float g_part[Bb * NCHUNK * Dd];    // unnormalized sigma partials
__device__ float g_Z[Bb * NCHUNK];            // per-chunk mass
__device__ float g_b[Bb * Nn];

namespace {
struct StreamKit {
    cudaStream_t s1;
    cudaEvent_t ev_root;
    cudaEvent_t ev_fill[NGRP];
    StreamKit() {
        cudaStreamCreateWithFlags(&s1, cudaStreamNonBlocking);
        cudaEventCreateWithFlags(&ev_root, cudaEventDisableTiming);
        for (int i = 0; i < NGRP; i++)
            cudaEventCreateWithFlags(&ev_fill[i], cudaEventDisableTiming);
    }
};
StreamKit g_kit;
}

__device__ __forceinline__ unsigned int pack2(float a, float b) {
    __half2 h = __floats2half2_rn(a, b);
    return *reinterpret_cast<unsigned int*>(&h);
}
__device__ __forceinline__ float2 unpack2(unsigned int u) {
    return __half22float2(*reinterpret_cast<__half2*>(&u));
}
// Warp sum via fixed-point integer redux (one instruction, all lanes).
__device__ __forceinline__ float warp_sum_fx(float v) {
    int iv = __float2int_rn(v * FXS);
    int r;
    asm volatile("redux.sync.add.s32 %0, %1, 0xffffffff;" : "=r"(r) : "r"(iv));
    return (float)r * FXI;
}

// ---------------- fill kernel: y = m*x (fp16) + sigma1 partials -----------
__global__ void __launch_bounds__(256, 4) fill_kernel(
    const float* x, const float* __restrict__ m, int b0) {
    const int b = b0 + blockIdx.y;
    const int c = blockIdx.x;
    const int t = threadIdx.x, w = t >> 5, l = t & 31;
    const int n0 = c * ROWS;

    __shared__ float m_sh[ROWS];
    __shared__ float sm_acc[WARPS * Dd];

    if (t < ROWS) m_sh[t] = m[b * Nn + n0 + t];
    __syncthreads();

    const size_t rowbase = (size_t)b * Nn + n0;
    const float* xb = x + rowbase * Dd;
    const int d0 = l << 2;

    float4 pa[PFF], pb[PFF];
#pragma unroll
    for (int j = 0; j < PFF; j++) {
        const float* xr = xb + (size_t)(w * RPW + j) * Dd;
        pa[j] = *reinterpret_cast<const float4*>(xr + d0);
        pb[j] = *reinterpret_cast<const float4*>(xr + 128 + d0);
    }

    float acc[8] = {0, 0, 0, 0, 0, 0, 0, 0};
#pragma unroll
    for (int i = 0; i < RPW; i++) {
        const int n = w * RPW + i;
        const float4 a0 = pa[i % PFF];
        const float4 a1 = pb[i % PFF];
        if (i + PFF < RPW) {
            const float* xn = xb + (size_t)(n + PFF) * Dd;
            pa[i % PFF] = *reinterpret_cast<const float4*>(xn + d0);
            pb[i % PFF] = *reinterpret_cast<const float4*>(xn + 128 + d0);
        }
        const float mn = m_sh[n];
        const float y0 = mn * a0.x, y1 = mn * a0.y, y2 = mn * a0.z, y3 = mn * a0.w;
        const float y4 = mn * a1.x, y5 = mn * a1.y, y6 = mn * a1.z, y7 = mn * a1.w;
        acc[0] += y0; acc[1] += y1; acc[2] += y2; acc[3] += y3;
        acc[4] += y4; acc[5] += y5; acc[6] += y6; acc[7] += y7;
        uint2 ua = make_uint2(pack2(y0, y1), pack2(y2, y3));
        uint2 ub = make_uint2(pack2(y4, y5), pack2(y6, y7));
        __half* yr = g_y + (rowbase + n) * Dd;
        *reinterpret_cast<uint2*>(yr + d0) = ua;
        *reinterpret_cast<uint2*>(yr + 128 + d0) = ub;
    }

    *reinterpret_cast<float4*>(&sm_acc[w * Dd + d0]) =
        make_float4(acc[0], acc[1], acc[2], acc[3]);
    *reinterpret_cast<float4*>(&sm_acc[w * Dd + 128 + d0]) =
        make_float4(acc[4], acc[5], acc[6], acc[7]);
    __syncthreads();

    float sig = 0.0f;
#pragma unroll
    for (int k = 0; k < WARPS; k++) sig += sm_acc[k * Dd + t];
    g_part[((size_t)b * NCHUNK + c) * Dd + t] = sig;
    if (t == 0) g_Z[b * NCHUNK + c] = (float)ROWS;  // uniform weights mass
}

// ------------- reuse kernel: head-combine -> s; b += dot; sigma ----------
// FINAL=false: also accumulate next sigma partials (exp weights).
// FINAL=true : write s to out_s; b-update only.
template <bool FINAL, bool ZEROB>
__global__ void __launch_bounds__(256, 5) reuse_kernel(
    const float* __restrict__ m, int b0, float* __restrict__ out_s) {
    const int b = b0 + blockIdx.y;
    const int c = blockIdx.x;
    const int t = threadIdx.x, w = t >> 5, l = t & 31;
    const int n0 = c * ROWS;

    __shared__ float s_sh[Dd];
    __shared__ float m_sh[ROWS];
    __shared__ float b_sh[ROWS];
    __shared__ float sm_acc[WARPS * Dd];
    __shared__ float sm_Z[WARPS];
    __shared__ float red[256];
    __shared__ float hz[NCHUNK];

    {
        int gi = b * Nn + n0;
        if (t < ROWS) {
            m_sh[t] = m[gi + t];
            b_sh[t] = ZEROB ? 0.0f : g_b[gi + t];
        }
    }
    // head-combine: rebuild s from previous sweep's partials
    if (t < NCHUNK) hz[t] = g_Z[b * NCHUNK + t];
    __syncthreads();
    {
        float v = 0.0f, Zg = 0.0f;
#pragma unroll
        for (int k = 0; k < NCHUNK; k++) {
            v += g_part[((size_t)b * NCHUNK + k) * Dd + t];
            Zg += hz[k];
        }
        const float sigma = v / Zg;
        red[t] = sigma * sigma;
        __syncthreads();
#pragma unroll
        for (int s = 128; s > 0; s >>= 1) {
            if (t < s) red[t] += red[t + s];
            __syncthreads();
        }
        const float n2 = red[0];
        const float norm = sqrtf(n2);
        const float sv = (n2 / (1.0f + n2) / (norm + 1e-8f)) * sigma;
        s_sh[t] = sv;
        if (FINAL && c == 0 && out_s) out_s[b * Dd + t] = sv;
    }
    __syncthreads();

    const size_t rowbase = (size_t)b * Nn + n0;
    const __half* yb = g_y + rowbase * Dd;
    const int h0 = l << 3;  // lane owns 8 halfs at h0

    // s values for this lane's columns, held in registers
    const float s0 = s_sh[h0],     s1 = s_sh[h0 + 1],
                s2 = s_sh[h0 + 2], s3 = s_sh[h0 + 3];
    const float s4 = s_sh[h0 + 4], s5 = s_sh[h0 + 5],
                s6 = s_sh[h0 + 6], s7 = s_sh[h0 + 7];

    uint4 py[PFR];
#pragma unroll
    for (int j = 0; j < PFR; j++)
        py[j] = *reinterpret_cast<const uint4*>(yb + (size_t)(w * RPW + j) * Dd + h0);

    float acc[8] = {0, 0, 0, 0, 0, 0, 0, 0};
    float Z = 0.0f;

#pragma unroll
    for (int i = 0; i < RPW; i++) {
        const int n = w * RPW + i;
        const uint4 u = py[i % PFR];
        if (i + PFR < RPW)
            py[i % PFR] = *reinterpret_cast<const uint4*>(
                yb + (size_t)(n + PFR) * Dd + h0);

        const float2 f0 = unpack2(u.x), f1 = unpack2(u.y),
                     f2 = unpack2(u.z), f3 = unpack2(u.w);

        float part = f0.x * s0 + f0.y * s1 + f1.x * s2 + f1.y * s3 +
                     f2.x * s4 + f2.y * s5 + f3.x * s6 + f3.y * s7;
        const float dot = warp_sum_fx(part);     // one-redux warp reduction

        const float bnew = b_sh[n] + dot;        // y already includes m
        if (l == 0) g_b[b * Nn + n0 + n] = bnew;

        if (!FINAL) {
            const float e = __expf(m_sh[n] * bnew);  // raw weight (|logit|<=~24)
            Z += e;
            acc[0] = fmaf(e, f0.x, acc[0]);
            acc[1] = fmaf(e, f0.y, acc[1]);
            acc[2] = fmaf(e, f1.x, acc[2]);
            acc[3] = fmaf(e, f1.y, acc[3]);
            acc[4] = fmaf(e, f2.x, acc[4]);
            acc[5] = fmaf(e, f2.y, acc[5]);
            acc[6] = fmaf(e, f3.x, acc[6]);
            acc[7] = fmaf(e, f3.y, acc[7]);
        }
    }

    if (!FINAL) {
        *reinterpret_cast<float4*>(&sm_acc[w * Dd + h0]) =
            make_float4(acc[0], acc[1], acc[2], acc[3]);
        *reinterpret_cast<float4*>(&sm_acc[w * Dd + h0 + 4]) =
            make_float4(acc[4], acc[5], acc[6], acc[7]);
        if (l == 0) sm_Z[w] = Z;
        __syncthreads();

        float sig = 0.0f;
#pragma unroll
        for (int k = 0; k < WARPS; k++) sig += sm_acc[k * Dd + t];
        g_part[((size_t)b * NCHUNK + c) * Dd + t] = sig;
        if (t == 0) {
            float Zb = 0.0f;
#pragma unroll
            for (int k = 0; k < WARPS; k++) Zb += sm_Z[k];
            g_Z[b * NCHUNK + c] = Zb;
        }
    }
}

// Final w = softmax(b) over N (no m factor). Exact 2-pass in-register.
__global__ void __launch_bounds__(256) final_softmax_kernel(float* __restrict__ out_w) {
    const int b = blockIdx.x, t = threadIdx.x;
    const float* bb = g_b + (size_t)b * Nn;

    float vals[16];
    float lmax = -3.4e38f;
#pragma unroll
    for (int i = 0; i < 16; i++) {
        vals[i] = bb[t + i * 256];
        lmax = fmaxf(lmax, vals[i]);
    }
    __shared__ float red[256];
    red[t] = lmax;
    __syncthreads();
#pragma unroll
    for (int s = 128; s > 0; s >>= 1) {
        if (t < s) red[t] = fmaxf(red[t], red[t + s]);
        __syncthreads();
    }
    const float gmax = red[0];
    __syncthreads();

    float lsum = 0.0f;
#pragma unroll
    for (int i = 0; i < 16; i++) {
        vals[i] = __expf(vals[i] - gmax);
        lsum += vals[i];
    }
    red[t] = lsum;
    __syncthreads();
#pragma unroll
    for (int s = 128; s > 0; s >>= 1) {
        if (t < s) red[t] += red[t + s];
        __syncthreads();
    }
    const float inv = 1.0f / red[0];
#pragma unroll
    for (int i = 0; i < 16; i++)
        out_w[(size_t)b * Nn + t + i * 256] = vals[i] * inv;
}

extern "C" void kernel_launch(void* const* d_in, const int* in_sizes, int n_in,
                              void* d_out, int out_size) {
    (void)in_sizes; (void)n_in; (void)out_size;
    const float* x = (const float*)d_in[0];
    const float* m = (const float*)d_in[1];
    float* out = (float*)d_out;
    float* out_w = out;             // [B, N]
    float* out_s = out + Bb * Nn;   // [B, D]

    const dim3 grid(NCHUNK, GRP);

    // Fork side stream into the capture.
    cudaEventRecord(g_kit.ev_root, 0);
    cudaStreamWaitEvent(g_kit.s1, g_kit.ev_root, 0);

    for (int g = 0; g < NGRP; ++g) {
        fill_kernel<<<grid, 256, 0, g_kit.s1>>>(x, m, g * GRP);
        cudaEventRecord(g_kit.ev_fill[g], g_kit.s1);
    }

    for (int g = 0; g < NGRP; ++g) {
        const int b0 = g * GRP;
        cudaStreamWaitEvent(0, g_kit.ev_fill[g], 0);
        reuse_kernel<false, true><<<grid, 256>>>(m, b0, nullptr);   // b1+sigma2
        reuse_kernel<false, false><<<grid, 256>>>(m, b0, nullptr);  // b2+sigma3
        reuse_kernel<true, false><<<grid, 256>>>(m, b0, out_s);     // s3+b3
    }
    final_softmax_kernel<<<Bb, 256>>>(out_w);  // w = softmax(b3)
}

// round 14
// speedup vs baseline: 1.1142x; 1.1142x over previous
#include <cuda_runtime.h>
#include <cuda_fp16.h>
#include <cstdint>

// DynamicPooling R14: R11 config (shfl butterfly, lb(256,4)) + split kernels
// + ONE change: loop-invariant s values hoisted from shared into registers
// (removes 8 LDS per row from the MIO pipe, the measured binder).
// B=64, N=4096, D=256. x f32 [B,N,D], m f32 [B,N,1]. Out: w [B,N], s [B,D].

namespace {
constexpr int Bb = 64;
constexpr int Nn = 4096;
constexpr int Dd = 256;
constexpr int NCHUNK = 32;            // N-chunks per batch
constexpr int ROWS = Nn / NCHUNK;     // 128 rows per block
constexpr int WARPS = 8;
constexpr int RPW = ROWS / WARPS;     // 16 rows per warp
constexpr int GRP = 16;               // batches per group
constexpr int NGRP = Bb / GRP;        // 4 groups
constexpr int PFF = 3;                // prefetch depth, fill (DRAM, f32)
constexpr int PFR = 2;                // prefetch depth, reuse (L2, fp16)
}

__device__ __half g_y[(size_t)Bb * Nn * Dd];  // fp16 cache of m*x (128MB)
__device__ float g_part[Bb * NCHUNK * Dd];    // unnormalized sigma partials
__device__ float g_Z[Bb * NCHUNK];            // per-chunk mass
__device__ float g_b[Bb * Nn];

namespace {
struct StreamKit {
    cudaStream_t s1;
    cudaEvent_t ev_root;
    cudaEvent_t ev_fill[NGRP];
    StreamKit() {
        cudaStreamCreateWithFlags(&s1, cudaStreamNonBlocking);
        cudaEventCreateWithFlags(&ev_root, cudaEventDisableTiming);
        for (int i = 0; i < NGRP; i++)
            cudaEventCreateWithFlags(&ev_fill[i], cudaEventDisableTiming);
    }
};
StreamKit g_kit;
}

__device__ __forceinline__ unsigned int pack2(float a, float b) {
    __half2 h = __floats2half2_rn(a, b);
    return *reinterpret_cast<unsigned int*>(&h);
}
__device__ __forceinline__ float2 unpack2(unsigned int u) {
    return __half22float2(*reinterpret_cast<__half2*>(&u));
}

// ---------------- fill kernel: y = m*x (fp16) + sigma1 partials -----------
__global__ void __launch_bounds__(256, 4) fill_kernel(
    const float* x, const float* __restrict__ m, int b0) {
    const int b = b0 + blockIdx.y;
    const int c = blockIdx.x;
    const int t = threadIdx.x, w = t >> 5, l = t & 31;
    const int n0 = c * ROWS;

    __shared__ float m_sh[ROWS];
    __shared__ float sm_acc[WARPS * Dd];

    if (t < ROWS) m_sh[t] = m[b * Nn + n0 + t];
    __syncthreads();

    const size_t rowbase = (size_t)b * Nn + n0;
    const float* xb = x + rowbase * Dd;
    const int d0 = l << 2;

    float4 pa[PFF], pb[PFF];
#pragma unroll
    for (int j = 0; j < PFF; j++) {
        const float* xr = xb + (size_t)(w * RPW + j) * Dd;
        pa[j] = *reinterpret_cast<const float4*>(xr + d0);
        pb[j] = *reinterpret_cast<const float4*>(xr + 128 + d0);
    }

    float acc[8] = {0, 0, 0, 0, 0, 0, 0, 0};
#pragma unroll
    for (int i = 0; i < RPW; i++) {
        const int n = w * RPW + i;
        const float4 a0 = pa[i % PFF];
        const float4 a1 = pb[i % PFF];
        if (i + PFF < RPW) {
            const float* xn = xb + (size_t)(n + PFF) * Dd;
            pa[i % PFF] = *reinterpret_cast<const float4*>(xn + d0);
            pb[i % PFF] = *reinterpret_cast<const float4*>(xn + 128 + d0);
        }
        const float mn = m_sh[n];
        const float y0 = mn * a0.x, y1 = mn * a0.y, y2 = mn * a0.z, y3 = mn * a0.w;
        const float y4 = mn * a1.x, y5 = mn * a1.y, y6 = mn * a1.z, y7 = mn * a1.w;
        acc[0] += y0; acc[1] += y1; acc[2] += y2; acc[3] += y3;
        acc[4] += y4; acc[5] += y5; acc[6] += y6; acc[7] += y7;
        uint2 ua = make_uint2(pack2(y0, y1), pack2(y2, y3));
        uint2 ub = make_uint2(pack2(y4, y5), pack2(y6, y7));
        __half* yr = g_y + (rowbase + n) * Dd;
        *reinterpret_cast<uint2*>(yr + d0) = ua;
        *reinterpret_cast<uint2*>(yr + 128 + d0) = ub;
    }

    *reinterpret_cast<float4*>(&sm_acc[w * Dd + d0]) =
        make_float4(acc[0], acc[1], acc[2], acc[3]);
    *reinterpret_cast<float4*>(&sm_acc[w * Dd + 128 + d0]) =
        make_float4(acc[4], acc[5], acc[6], acc[7]);
    __syncthreads();

    float sig = 0.0f;
#pragma unroll
    for (int k = 0; k < WARPS; k++) sig += sm_acc[k * Dd + t];
    g_part[((size_t)b * NCHUNK + c) * Dd + t] = sig;
    if (t == 0) g_Z[b * NCHUNK + c] = (float)ROWS;  // uniform weights mass
}

// ------------- reuse kernel: head-combine -> s; b += dot; sigma ----------
// FINAL=false: also accumulate next sigma partials (exp weights).
// FINAL=true : write s to out_s; b-update only.
template <bool FINAL, bool ZEROB>
__global__ void __launch_bounds__(256, 4) reuse_kernel(
    const float* __restrict__ m, int b0, float* __restrict__ out_s) {
    const int b = b0 + blockIdx.y;
    const int c = blockIdx.x;
    const int t = threadIdx.x, w = t >> 5, l = t & 31;
    const int n0 = c * ROWS;

    __shared__ float s_sh[Dd];
    __shared__ float m_sh[ROWS];
    __shared__ float b_sh[ROWS];
    __shared__ float sm_acc[WARPS * Dd];
    __shared__ float sm_Z[WARPS];
    __shared__ float red[256];
    __shared__ float hz[NCHUNK];

    {
        int gi = b * Nn + n0;
        if (t < ROWS) {
            m_sh[t] = m[gi + t];
            b_sh[t] = ZEROB ? 0.0f : g_b[gi + t];
        }
    }
    // head-combine: rebuild s from previous sweep's partials
    if (t < NCHUNK) hz[t] = g_Z[b * NCHUNK + t];
    __syncthreads();
    {
        float v = 0.0f, Zg = 0.0f;
#pragma unroll
        for (int k = 0; k < NCHUNK; k++) {
            v += g_part[((size_t)b * NCHUNK + k) * Dd + t];
            Zg += hz[k];
        }
        const float sigma = v / Zg;
        red[t] = sigma * sigma;
        __syncthreads();
#pragma unroll
        for (int s = 128; s > 0; s >>= 1) {
            if (t < s) red[t] += red[t + s];
            __syncthreads();
        }
        const float n2 = red[0];
        const float norm = sqrtf(n2);
        const float sv = (n2 / (1.0f + n2) / (norm + 1e-8f)) * sigma;
        s_sh[t] = sv;
        if (FINAL && c == 0 && out_s) out_s[b * Dd + t] = sv;
    }
    __syncthreads();

    const size_t rowbase = (size_t)b * Nn + n0;
    const __half* yb = g_y + rowbase * Dd;
    const int h0 = l << 3;  // lane owns 8 halfs at h0

    // loop-invariant s values hoisted into registers (saves 8 LDS per row)
    const float s0 = s_sh[h0],     s1 = s_sh[h0 + 1],
                s2 = s_sh[h0 + 2], s3 = s_sh[h0 + 3];
    const float s4 = s_sh[h0 + 4], s5 = s_sh[h0 + 5],
                s6 = s_sh[h0 + 6], s7 = s_sh[h0 + 7];

    uint4 py[PFR];
#pragma unroll
    for (int j = 0; j < PFR; j++)
        py[j] = *reinterpret_cast<const uint4*>(yb + (size_t)(w * RPW + j) * Dd + h0);

    float acc[8] = {0, 0, 0, 0, 0, 0, 0, 0};
    float Z = 0.0f;

#pragma unroll
    for (int i = 0; i < RPW; i++) {
        const int n = w * RPW + i;
        const uint4 u = py[i % PFR];
        if (i + PFR < RPW)
            py[i % PFR] = *reinterpret_cast<const uint4*>(
                yb + (size_t)(n + PFR) * Dd + h0);

        const float2 f0 = unpack2(u.x), f1 = unpack2(u.y),
                     f2 = unpack2(u.z), f3 = unpack2(u.w);

        float dot = f0.x * s0 + f0.y * s1 + f1.x * s2 + f1.y * s3 +
                    f2.x * s4 + f2.y * s5 + f3.x * s6 + f3.y * s7;
#pragma unroll
        for (int o = 16; o > 0; o >>= 1)
            dot += __shfl_xor_sync(0xffffffffu, dot, o);

        const float bnew = b_sh[n] + dot;        // y already includes m
        if (l == 0) g_b[b * Nn + n0 + n] = bnew;

        if (!FINAL) {
            const float e = __expf(m_sh[n] * bnew);  // raw weight (|logit|<=~24)
            Z += e;
            acc[0] = fmaf(e, f0.x, acc[0]);
            acc[1] = fmaf(e, f0.y, acc[1]);
            acc[2] = fmaf(e, f1.x, acc[2]);
            acc[3] = fmaf(e, f1.y, acc[3]);
            acc[4] = fmaf(e, f2.x, acc[4]);
            acc[5] = fmaf(e, f2.y, acc[5]);
            acc[6] = fmaf(e, f3.x, acc[6]);
            acc[7] = fmaf(e, f3.y, acc[7]);
        }
    }

    if (!FINAL) {
        *reinterpret_cast<float4*>(&sm_acc[w * Dd + h0]) =
            make_float4(acc[0], acc[1], acc[2], acc[3]);
        *reinterpret_cast<float4*>(&sm_acc[w * Dd + h0 + 4]) =
            make_float4(acc[4], acc[5], acc[6], acc[7]);
        if (l == 0) sm_Z[w] = Z;
        __syncthreads();

        float sig = 0.0f;
#pragma unroll
        for (int k = 0; k < WARPS; k++) sig += sm_acc[k * Dd + t];
        g_part[((size_t)b * NCHUNK + c) * Dd + t] = sig;
        if (t == 0) {
            float Zb = 0.0f;
#pragma unroll
            for (int k = 0; k < WARPS; k++) Zb += sm_Z[k];
            g_Z[b * NCHUNK + c] = Zb;
        }
    }
}

// Final w = softmax(b) over N (no m factor). Exact 2-pass in-register.
__global__ void __launch_bounds__(256) final_softmax_kernel(float* __restrict__ out_w) {
    const int b = blockIdx.x, t = threadIdx.x;
    const float* bb = g_b + (size_t)b * Nn;

    float vals[16];
    float lmax = -3.4e38f;
#pragma unroll
    for (int i = 0; i < 16; i++) {
        vals[i] = bb[t + i * 256];
        lmax = fmaxf(lmax, vals[i]);
    }
    __shared__ float red[256];
    red[t] = lmax;
    __syncthreads();
#pragma unroll
    for (int s = 128; s > 0; s >>= 1) {
        if (t < s) red[t] = fmaxf(red[t], red[t + s]);
        __syncthreads();
    }
    const float gmax = red[0];
    __syncthreads();

    float lsum = 0.0f;
#pragma unroll
    for (int i = 0; i < 16; i++) {
        vals[i] = __expf(vals[i] - gmax);
        lsum += vals[i];
    }
    red[t] = lsum;
    __syncthreads();
#pragma unroll
    for (int s = 128; s > 0; s >>= 1) {
        if (t < s) red[t] += red[t + s];
        __syncthreads();
    }
    const float inv = 1.0f / red[0];
#pragma unroll
    for (int i = 0; i < 16; i++)
        out_w[(size_t)b * Nn + t + i * 256] = vals[i] * inv;
}

extern "C" void kernel_launch(void* const* d_in, const int* in_sizes, int n_in,
                              void* d_out, int out_size) {
    (void)in_sizes; (void)n_in; (void)out_size;
    const float* x = (const float*)d_in[0];
    const float* m = (const float*)d_in[1];
    float* out = (float*)d_out;
    float* out_w = out;             // [B, N]
    float* out_s = out + Bb * Nn;   // [B, D]

    const dim3 grid(NCHUNK, GRP);

    // Fork side stream into the capture.
    cudaEventRecord(g_kit.ev_root, 0);
    cudaStreamWaitEvent(g_kit.s1, g_kit.ev_root, 0);

    for (int g = 0; g < NGRP; ++g) {
        fill_kernel<<<grid, 256, 0, g_kit.s1>>>(x, m, g * GRP);
        cudaEventRecord(g_kit.ev_fill[g], g_kit.s1);
    }

    for (int g = 0; g < NGRP; ++g) {
        const int b0 = g * GRP;
        cudaStreamWaitEvent(0, g_kit.ev_fill[g], 0);
        reuse_kernel<false, true><<<grid, 256>>>(m, b0, nullptr);   // b1+sigma2
        reuse_kernel<false, false><<<grid, 256>>>(m, b0, nullptr);  // b2+sigma3
        reuse_kernel<true, false><<<grid, 256>>>(m, b0, out_s);     // s3+b3
    }
    final_softmax_kernel<<<Bb, 256>>>(out_w);  // w = softmax(b3)
}

// round 15
// speedup vs baseline: 1.1257x; 1.0103x over previous
#include <cuda_runtime.h>
#include <cuda_fp16.h>
#include <cstdint>

// DynamicPooling R15: R14 + packed f32x2 math in the reuse inner loop
// (fma.rn.f32x2 — PTX-only dual-lane FP32 FMA on sm_103), PFR=3.
// B=64, N=4096, D=256. x f32 [B,N,D], m f32 [B,N,1]. Out: w [B,N], s [B,D].

namespace {
constexpr int Bb = 64;
constexpr int Nn = 4096;
constexpr int Dd = 256;
constexpr int NCHUNK = 32;            // N-chunks per batch
constexpr int ROWS = Nn / NCHUNK;     // 128 rows per block
constexpr int WARPS = 8;
constexpr int RPW = ROWS / WARPS;     // 16 rows per warp
constexpr int GRP = 16;               // batches per group
constexpr int NGRP = Bb / GRP;        // 4 groups
constexpr int PFF = 3;                // prefetch depth, fill (DRAM, f32)
constexpr int PFR = 3;                // prefetch depth, reuse (L2, fp16)
}

__device__ __half g_y[(size_t)Bb * Nn * Dd];  // fp16 cache of m*x (128MB)
__device__ float g_part[Bb * NCHUNK * Dd];    // unnormalized sigma partials
__device__ float g_Z[Bb * NCHUNK];            // per-chunk mass
__device__ float g_b[Bb * Nn];

namespace {
struct StreamKit {
    cudaStream_t s1;
    cudaEvent_t ev_root;
    cudaEvent_t ev_fill[NGRP];
    StreamKit() {
        cudaStreamCreateWithFlags(&s1, cudaStreamNonBlocking);
        cudaEventCreateWithFlags(&ev_root, cudaEventDisableTiming);
        for (int i = 0; i < NGRP; i++)
            cudaEventCreateWithFlags(&ev_fill[i], cudaEventDisableTiming);
    }
};
StreamKit g_kit;
}

__device__ __forceinline__ unsigned int pack2(float a, float b) {
    __half2 h = __floats2half2_rn(a, b);
    return *reinterpret_cast<unsigned int*>(&h);
}
__device__ __forceinline__ float2 unpack2(unsigned int u) {
    return __half22float2(*reinterpret_cast<__half2*>(&u));
}

// ---- packed f32x2 helpers (dual-lane fp32; IEEE per lane == scalar fma) ----
__device__ __forceinline__ unsigned long long pk(float lo, float hi) {
    unsigned long long r;
    asm("mov.b64 %0, {%1, %2};" : "=l"(r) : "f"(lo), "f"(hi));
    return r;
}
__device__ __forceinline__ float2 upk(unsigned long long v) {
    float2 r;
    asm("mov.b64 {%0, %1}, %2;" : "=f"(r.x), "=f"(r.y) : "l"(v));
    return r;
}
__device__ __forceinline__ unsigned long long mul2(unsigned long long a,
                                                   unsigned long long b) {
    unsigned long long r;
    asm("mul.rn.f32x2 %0, %1, %2;" : "=l"(r) : "l"(a), "l"(b));
    return r;
}
__device__ __forceinline__ unsigned long long fma2(unsigned long long a,
                                                   unsigned long long b,
                                                   unsigned long long c) {
    unsigned long long r;
    asm("fma.rn.f32x2 %0, %1, %2, %3;" : "=l"(r) : "l"(a), "l"(b), "l"(c));
    return r;
}

// ---------------- fill kernel: y = m*x (fp16) + sigma1 partials -----------
__global__ void __launch_bounds__(256, 4) fill_kernel(
    const float* x, const float* __restrict__ m, int b0) {
    const int b = b0 + blockIdx.y;
    const int c = blockIdx.x;
    const int t = threadIdx.x, w = t >> 5, l = t & 31;
    const int n0 = c * ROWS;

    __shared__ float m_sh[ROWS];
    __shared__ float sm_acc[WARPS * Dd];

    if (t < ROWS) m_sh[t] = m[b * Nn + n0 + t];
    __syncthreads();

    const size_t rowbase = (size_t)b * Nn + n0;
    const float* xb = x + rowbase * Dd;
    const int d0 = l << 2;

    float4 pa[PFF], pb[PFF];
#pragma unroll
    for (int j = 0; j < PFF; j++) {
        const float* xr = xb + (size_t)(w * RPW + j) * Dd;
        pa[j] = *reinterpret_cast<const float4*>(xr + d0);
        pb[j] = *reinterpret_cast<const float4*>(xr + 128 + d0);
    }

    float acc[8] = {0, 0, 0, 0, 0, 0, 0, 0};
#pragma unroll
    for (int i = 0; i < RPW; i++) {
        const int n = w * RPW + i;
        const float4 a0 = pa[i % PFF];
        const float4 a1 = pb[i % PFF];
        if (i + PFF < RPW) {
            const float* xn = xb + (size_t)(n + PFF) * Dd;
            pa[i % PFF] = *reinterpret_cast<const float4*>(xn + d0);
            pb[i % PFF] = *reinterpret_cast<const float4*>(xn + 128 + d0);
        }
        const float mn = m_sh[n];
        const float y0 = mn * a0.x, y1 = mn * a0.y, y2 = mn * a0.z, y3 = mn * a0.w;
        const float y4 = mn * a1.x, y5 = mn * a1.y, y6 = mn * a1.z, y7 = mn * a1.w;
        acc[0] += y0; acc[1] += y1; acc[2] += y2; acc[3] += y3;
        acc[4] += y4; acc[5] += y5; acc[6] += y6; acc[7] += y7;
        uint2 ua = make_uint2(pack2(y0, y1), pack2(y2, y3));
        uint2 ub = make_uint2(pack2(y4, y5), pack2(y6, y7));
        __half* yr = g_y + (rowbase + n) * Dd;
        *reinterpret_cast<uint2*>(yr + d0) = ua;
        *reinterpret_cast<uint2*>(yr + 128 + d0) = ub;
    }

    *reinterpret_cast<float4*>(&sm_acc[w * Dd + d0]) =
        make_float4(acc[0], acc[1], acc[2], acc[3]);
    *reinterpret_cast<float4*>(&sm_acc[w * Dd + 128 + d0]) =
        make_float4(acc[4], acc[5], acc[6], acc[7]);
    __syncthreads();

    float sig = 0.0f;
#pragma unroll
    for (int k = 0; k < WARPS; k++) sig += sm_acc[k * Dd + t];
    g_part[((size_t)b * NCHUNK + c) * Dd + t] = sig;
    if (t == 0) g_Z[b * NCHUNK + c] = (float)ROWS;  // uniform weights mass
}

// ------------- reuse kernel: head-combine -> s; b += dot; sigma ----------
// FINAL=false: also accumulate next sigma partials (exp weights).
// FINAL=true : write s to out_s; b-update only.
template <bool FINAL, bool ZEROB>
__global__ void __launch_bounds__(256, 4) reuse_kernel(
    const float* __restrict__ m, int b0, float* __restrict__ out_s) {
    const int b = b0 + blockIdx.y;
    const int c = blockIdx.x;
    const int t = threadIdx.x, w = t >> 5, l = t & 31;
    const int n0 = c * ROWS;

    __shared__ float s_sh[Dd];
    __shared__ float m_sh[ROWS];
    __shared__ float b_sh[ROWS];
    __shared__ float sm_acc[WARPS * Dd];
    __shared__ float sm_Z[WARPS];
    __shared__ float red[256];
    __shared__ float hz[NCHUNK];

    {
        int gi = b * Nn + n0;
        if (t < ROWS) {
            m_sh[t] = m[gi + t];
            b_sh[t] = ZEROB ? 0.0f : g_b[gi + t];
        }
    }
    // head-combine: rebuild s from previous sweep's partials
    if (t < NCHUNK) hz[t] = g_Z[b * NCHUNK + t];
    __syncthreads();
    {
        float v = 0.0f, Zg = 0.0f;
#pragma unroll
        for (int k = 0; k < NCHUNK; k++) {
            v += g_part[((size_t)b * NCHUNK + k) * Dd + t];
            Zg += hz[k];
        }
        const float sigma = v / Zg;
        red[t] = sigma * sigma;
        __syncthreads();
#pragma unroll
        for (int s = 128; s > 0; s >>= 1) {
            if (t < s) red[t] += red[t + s];
            __syncthreads();
        }
        const float n2 = red[0];
        const float norm = sqrtf(n2);
        const float sv = (n2 / (1.0f + n2) / (norm + 1e-8f)) * sigma;
        s_sh[t] = sv;
        if (FINAL && c == 0 && out_s) out_s[b * Dd + t] = sv;
    }
    __syncthreads();

    const size_t rowbase = (size_t)b * Nn + n0;
    const __half* yb = g_y + rowbase * Dd;
    const int h0 = l << 3;  // lane owns 8 halfs at h0

    // loop-invariant s values packed into f32x2 registers
    const unsigned long long sp0 = pk(s_sh[h0],     s_sh[h0 + 1]);
    const unsigned long long sp1 = pk(s_sh[h0 + 2], s_sh[h0 + 3]);
    const unsigned long long sp2 = pk(s_sh[h0 + 4], s_sh[h0 + 5]);
    const unsigned long long sp3 = pk(s_sh[h0 + 6], s_sh[h0 + 7]);

    uint4 py[PFR];
#pragma unroll
    for (int j = 0; j < PFR; j++)
        py[j] = *reinterpret_cast<const uint4*>(yb + (size_t)(w * RPW + j) * Dd + h0);

    // sigma accumulators as packed pairs (cols h0+0..7)
    unsigned long long ac0 = 0ull, ac1 = 0ull, ac2 = 0ull, ac3 = 0ull;
    float Z = 0.0f;

#pragma unroll
    for (int i = 0; i < RPW; i++) {
        const int n = w * RPW + i;
        const uint4 u = py[i % PFR];
        if (i + PFR < RPW)
            py[i % PFR] = *reinterpret_cast<const uint4*>(
                yb + (size_t)(n + PFR) * Dd + h0);

        const float2 f0 = unpack2(u.x), f1 = unpack2(u.y),
                     f2 = unpack2(u.z), f3 = unpack2(u.w);
        const unsigned long long yp0 = pk(f0.x, f0.y);
        const unsigned long long yp1 = pk(f1.x, f1.y);
        const unsigned long long yp2 = pk(f2.x, f2.y);
        const unsigned long long yp3 = pk(f3.x, f3.y);

        // dot partial via packed fma chain, then lo+hi
        unsigned long long d2 = mul2(yp0, sp0);
        d2 = fma2(yp1, sp1, d2);
        d2 = fma2(yp2, sp2, d2);
        d2 = fma2(yp3, sp3, d2);
        const float2 dd = upk(d2);
        float dot = dd.x + dd.y;
#pragma unroll
        for (int o = 16; o > 0; o >>= 1)
            dot += __shfl_xor_sync(0xffffffffu, dot, o);

        const float bnew = b_sh[n] + dot;        // y already includes m
        if (l == 0) g_b[b * Nn + n0 + n] = bnew;

        if (!FINAL) {
            const float e = __expf(m_sh[n] * bnew);  // raw weight (|logit|<=~24)
            Z += e;
            const unsigned long long e2 = pk(e, e);
            ac0 = fma2(e2, yp0, ac0);
            ac1 = fma2(e2, yp1, ac1);
            ac2 = fma2(e2, yp2, ac2);
            ac3 = fma2(e2, yp3, ac3);
        }
    }

    if (!FINAL) {
        const float2 a0 = upk(ac0), a1 = upk(ac1), a2 = upk(ac2), a3 = upk(ac3);
        *reinterpret_cast<float4*>(&sm_acc[w * Dd + h0]) =
            make_float4(a0.x, a0.y, a1.x, a1.y);
        *reinterpret_cast<float4*>(&sm_acc[w * Dd + h0 + 4]) =
            make_float4(a2.x, a2.y, a3.x, a3.y);
        if (l == 0) sm_Z[w] = Z;
        __syncthreads();

        float sig = 0.0f;
#pragma unroll
        for (int k = 0; k < WARPS; k++) sig += sm_acc[k * Dd + t];
        g_part[((size_t)b * NCHUNK + c) * Dd + t] = sig;
        if (t == 0) {
            float Zb = 0.0f;
#pragma unroll
            for (int k = 0; k < WARPS; k++) Zb += sm_Z[k];
            g_Z[b * NCHUNK + c] = Zb;
        }
    }
}

// Final w = softmax(b) over N (no m factor). Exact 2-pass in-register.
__global__ void __launch_bounds__(256) final_softmax_kernel(float* __restrict__ out_w) {
    const int b = blockIdx.x, t = threadIdx.x;
    const float* bb = g_b + (size_t)b * Nn;

    float vals[16];
    float lmax = -3.4e38f;
#pragma unroll
    for (int i = 0; i < 16; i++) {
        vals[i] = bb[t + i * 256];
        lmax = fmaxf(lmax, vals[i]);
    }
    __shared__ float red[256];
    red[t] = lmax;
    __syncthreads();
#pragma unroll
    for (int s = 128; s > 0; s >>= 1) {
        if (t < s) red[t] = fmaxf(red[t], red[t + s]);
        __syncthreads();
    }
    const float gmax = red[0];
    __syncthreads();

    float lsum = 0.0f;
#pragma unroll
    for (int i = 0; i < 16; i++) {
        vals[i] = __expf(vals[i] - gmax);
        lsum += vals[i];
    }
    red[t] = lsum;
    __syncthreads();
#pragma unroll
    for (int s = 128; s > 0; s >>= 1) {
        if (t < s) red[t] += red[t + s];
        __syncthreads();
    }
    const float inv = 1.0f / red[0];
#pragma unroll
    for (int i = 0; i < 16; i++)
        out_w[(size_t)b * Nn + t + i * 256] = vals[i] * inv;
}

extern "C" void kernel_launch(void* const* d_in, const int* in_sizes, int n_in,
                              void* d_out, int out_size) {
    (void)in_sizes; (void)n_in; (void)out_size;
    const float* x = (const float*)d_in[0];
    const float* m = (const float*)d_in[1];
    float* out = (float*)d_out;
    float* out_w = out;             // [B, N]
    float* out_s = out + Bb * Nn;   // [B, D]

    const dim3 grid(NCHUNK, GRP);

    // Fork side stream into the capture.
    cudaEventRecord(g_kit.ev_root, 0);
    cudaStreamWaitEvent(g_kit.s1, g_kit.ev_root, 0);

    for (int g = 0; g < NGRP; ++g) {
        fill_kernel<<<grid, 256, 0, g_kit.s1>>>(x, m, g * GRP);
        cudaEventRecord(g_kit.ev_fill[g], g_kit.s1);
    }

    for (int g = 0; g < NGRP; ++g) {
        const int b0 = g * GRP;
        cudaStreamWaitEvent(0, g_kit.ev_fill[g], 0);
        reuse_kernel<false, true><<<grid, 256>>>(m, b0, nullptr);   // b1+sigma2
        reuse_kernel<false, false><<<grid, 256>>>(m, b0, nullptr);  // b2+sigma3
        reuse_kernel<true, false><<<grid, 256>>>(m, b0, out_s);     // s3+b3
    }
    final_softmax_kernel<<<Bb, 256>>>(out_w);  // w = softmax(b3)
}